// round 1
// baseline (speedup 1.0000x reference)
#include <cuda_runtime.h>
#include <math.h>

#define NN 2048
#define TT 20
#define KK 32
#define CC 32
#define OO 64
#define G4 256   // 4*OO

// Scratch (static device globals; no runtime allocation)
__device__ float g_z[TT * NN * OO];        // z[t][n][o] = x[n][t] . conv_w[o]
__device__ float g_feat[TT * NN * OO];     // feat[t][n][o]
__device__ float g_gates[TT * NN * G4];    // gates_x[t][n][0..255]

__device__ __forceinline__ float sigf(float x) { return 1.0f / (1.0f + expf(-x)); }

// ---------------------------------------------------------------------------
// K1: z[t][n][o] = sum_c x[n][t][c] * conv_w[o][c]
// Block = 256 threads = 8 rows x 32 lanes; lane computes outputs {2l, 2l+1}.
// conv_w transposed into smem so weight LDS is conflict-free.
// ---------------------------------------------------------------------------
__global__ __launch_bounds__(256) void k1_project(const float* __restrict__ x,
                                                  const float* __restrict__ conv_w) {
    __shared__ float cwT[CC * OO];      // cwT[c*64 + o]
    __shared__ float xs[8][CC];

    const int tid = threadIdx.x;
    for (int e = tid; e < OO * CC; e += 256) {
        int o = e >> 5, c = e & 31;
        cwT[c * OO + o] = conv_w[e];
    }

    const int r = tid >> 5, lane = tid & 31;
    const int row = (blockIdx.x << 3) + r;          // row = t*N + n
    const int t = row >> 11, n = row & (NN - 1);
    xs[r][lane] = x[((n * TT + t) << 5) + lane];
    __syncthreads();

    float2 acc = make_float2(0.f, 0.f);
    const float2* cwT2 = (const float2*)cwT;
#pragma unroll
    for (int c = 0; c < CC; c++) {
        float xv = xs[r][c];
        float2 w2 = cwT2[c * 32 + lane];
        acc.x = fmaf(xv, w2.x, acc.x);
        acc.y = fmaf(xv, w2.y, acc.y);
    }
    ((float2*)g_z)[row * 32 + lane] = acc;
}

// ---------------------------------------------------------------------------
// K2: feat[t][n][o] = max_k z[t][A[t][n][k]][o] - z[t][n][o] + conv_b[o]
// One warp per (t,n); lane k holds its neighbor index, broadcast via shfl.
// Each lane owns a float2 of the 64-wide channel dim.
// ---------------------------------------------------------------------------
__global__ __launch_bounds__(256) void k2_gather_max(const int* __restrict__ A,
                                                     const float* __restrict__ conv_b) {
    const int wid = (blockIdx.x << 3) + (threadIdx.x >> 5);  // row = t*N + n
    const int lane = threadIdx.x & 31;
    const int t = wid >> 11;

    const int nb = A[(wid << 5) + lane];  // this lane's neighbor index
    const float2* z2 = (const float2*)g_z;

    float mx = -1e30f, my = -1e30f;
#pragma unroll
    for (int k = 0; k < KK; k++) {
        int r = __shfl_sync(0xffffffffu, nb, k);
        float2 v = __ldg(&z2[(((t << 11) + r) << 5) + lane]);
        mx = fmaxf(mx, v.x);
        my = fmaxf(my, v.y);
    }
    float2 zc = z2[(wid << 5) + lane];
    float2 cb = ((const float2*)conv_b)[lane];
    float2 o;
    o.x = mx - zc.x + cb.x;
    o.y = my - zc.y + cb.y;
    ((float2*)g_feat)[(wid << 5) + lane] = o;
}

// ---------------------------------------------------------------------------
// K3: gates_x[row][o] = feat[row][:] . w_ih[o][:] + (b_ih[o] + b_hh[o])
// Block = 256 threads, thread tid owns output column o = tid (w_ih row in 64
// regs), block processes 32 feat rows staged in smem (broadcast LDS.128).
// ---------------------------------------------------------------------------
__global__ __launch_bounds__(256) void k3_gates_gemm(const float* __restrict__ w_ih,
                                                     const float* __restrict__ b_ih,
                                                     const float* __restrict__ b_hh) {
    __shared__ float4 fs4[32 * 16];  // 32 rows x 64 floats
    const int tid = threadIdx.x;
    const int row0 = blockIdx.x << 5;

    const float4* f4 = ((const float4*)g_feat) + row0 * 16;
    fs4[tid] = f4[tid];
    fs4[tid + 256] = f4[tid + 256];

    float4 wreg[16];
    const float4* wp = ((const float4*)w_ih) + tid * 16;
#pragma unroll
    for (int j = 0; j < 16; j++) wreg[j] = wp[j];
    const float bias = b_ih[tid] + b_hh[tid];
    __syncthreads();

    for (int r = 0; r < 32; r += 2) {
        float a0 = bias, a1 = bias;
#pragma unroll
        for (int j = 0; j < 16; j++) {
            float4 w4 = wreg[j];
            float4 f0 = fs4[r * 16 + j];
            float4 f1 = fs4[r * 16 + 16 + j];
            a0 = fmaf(w4.x, f0.x, fmaf(w4.y, f0.y, fmaf(w4.z, f0.z, fmaf(w4.w, f0.w, a0))));
            a1 = fmaf(w4.x, f1.x, fmaf(w4.y, f1.y, fmaf(w4.z, f1.z, fmaf(w4.w, f1.w, a1))));
        }
        g_gates[(row0 + r) * G4 + tid] = a0;
        g_gates[(row0 + r + 1) * G4 + tid] = a1;
    }
}

// ---------------------------------------------------------------------------
// K4: persistent LSTM. Block = 256 threads handles 16 agents for all 20 steps.
// Matvec phase: thread tid owns gate output o = tid; w_hh row in 64 regs;
// h broadcast from smem (1 LDS.128 per 4 FMA-quads -> crossbar below limit).
// Update phase: thread owns (agent a_u, 4 channels) keeping c in registers.
// Agents are independent -> no inter-block sync needed across timesteps.
// ---------------------------------------------------------------------------
__global__ __launch_bounds__(256) void k4_lstm(const float* __restrict__ w_hh,
                                               float* __restrict__ out,
                                               int write_states) {
    __shared__ float h_s[16 * OO];    // h per agent
    __shared__ float g_s[16 * G4];    // gate pre-activations per agent

    const int tid = threadIdx.x;
    const int o = tid;                // gate output column
    const int ab = blockIdx.x << 4;   // agent base

    float4 wreg[16];
    const float4* wp = ((const float4*)w_hh) + o * 16;
#pragma unroll
    for (int j = 0; j < 16; j++) wreg[j] = wp[j];

    for (int e = tid; e < 16 * OO; e += 256) h_s[e] = 0.f;

    const int a_u = tid >> 4;   // agent for update phase
    const int q = tid & 15;     // float4 chunk within 64 channels
    float4 c4 = make_float4(0.f, 0.f, 0.f, 0.f);
    __syncthreads();

    for (int t = 0; t < TT; t++) {
        // ---- matvec: g[a][o] = gates_x[t][ab+a][o] + w_hh[o] . h[a] ----
        float acc[16];
        const float* gx = g_gates + (((size_t)(t << 11) + ab) << 8) + o;
#pragma unroll
        for (int a = 0; a < 16; a++) acc[a] = gx[a << 8];

        const float4* hs4 = (const float4*)h_s;
#pragma unroll
        for (int j = 0; j < 16; j++) {
            float4 wv = wreg[j];
#pragma unroll
            for (int a = 0; a < 16; a++) {
                float4 hv = hs4[(a << 4) + j];
                acc[a] = fmaf(wv.x, hv.x,
                         fmaf(wv.y, hv.y,
                         fmaf(wv.z, hv.z,
                         fmaf(wv.w, hv.w, acc[a]))));
            }
        }
#pragma unroll
        for (int a = 0; a < 16; a++) g_s[(a << 8) + o] = acc[a];
        __syncthreads();

        // ---- nonlinear update: gates order i, f, g, o ----
        const float4* g4 = (const float4*)g_s;
        float4 gi = g4[(a_u << 6) + q];
        float4 gf = g4[(a_u << 6) + 16 + q];
        float4 gg = g4[(a_u << 6) + 32 + q];
        float4 go = g4[(a_u << 6) + 48 + q];

        c4.x = sigf(gf.x) * c4.x + sigf(gi.x) * tanhf(gg.x);
        c4.y = sigf(gf.y) * c4.y + sigf(gi.y) * tanhf(gg.y);
        c4.z = sigf(gf.z) * c4.z + sigf(gi.z) * tanhf(gg.z);
        c4.w = sigf(gf.w) * c4.w + sigf(gi.w) * tanhf(gg.w);

        float4 h4;
        h4.x = sigf(go.x) * tanhf(c4.x);
        h4.y = sigf(go.y) * tanhf(c4.y);
        h4.z = sigf(go.z) * tanhf(c4.z);
        h4.w = sigf(go.w) * tanhf(c4.w);

        ((float4*)h_s)[(a_u << 4) + q] = h4;
        ((float4*)out)[(((ab + a_u) * TT + t) << 4) + q] = h4;  // out[n][t][:]
        __syncthreads();
    }

    if (write_states) {
        float4 h4 = ((const float4*)h_s)[(a_u << 4) + q];
        float4* hn = (float4*)(out + (size_t)NN * TT * OO);
        float4* cn = (float4*)(out + (size_t)NN * TT * OO + (size_t)NN * OO);
        hn[((ab + a_u) << 4) + q] = h4;
        cn[((ab + a_u) << 4) + q] = c4;
    }
}

// ---------------------------------------------------------------------------
extern "C" void kernel_launch(void* const* d_in, const int* in_sizes, int n_in,
                              void* d_out, int out_size) {
    const float* x      = (const float*)d_in[0];
    const int*   A      = (const int*)  d_in[1];
    const float* conv_w = (const float*)d_in[2];
    const float* conv_b = (const float*)d_in[3];
    const float* w_ih   = (const float*)d_in[4];
    const float* w_hh   = (const float*)d_in[5];
    const float* b_ih   = (const float*)d_in[6];
    const float* b_hh   = (const float*)d_in[7];
    float* out = (float*)d_out;

    const long main_sz = (long)NN * TT * OO;
    int write_states = (out_size >= main_sz + 2L * NN * OO) ? 1 : 0;

    k1_project<<<(TT * NN) / 8, 256>>>(x, conv_w);
    k2_gather_max<<<(TT * NN) / 8, 256>>>(A, conv_b);
    k3_gates_gemm<<<(TT * NN) / 32, 256>>>(w_ih, b_ih, b_hh);
    k4_lstm<<<NN / 16, 256>>>(w_hh, out, write_states);
}